// round 4
// baseline (speedup 1.0000x reference)
#include <cuda_runtime.h>
#include <math.h>

#define NPTS 4096
#define DIM  64
#define KNN  15
#define NNEG 32
#define TEMP_INV 10.0f
#define MARGIN 0.5f
#define FULLMASK 0xffffffffu

// ---------------- device scratch (allocation-free per rules) ----------------
__device__ float g_zr[NPTS * DIM];        // normalized z_rna
__device__ float g_za[NPTS * DIM];        // normalized z_atac
__device__ float g_anorm[NPTS];           // raw ||z_atac_i||
__device__ int   g_ir[NPTS * KNN];        // rna knn indices
__device__ float g_wr[NPTS * KNN];        // rna softmax weights
__device__ int   g_ia[NPTS * KNN];        // atac knn indices
__device__ float g_wa[NPTS * KNN];        // atac softmax weights
__device__ int   g_ineg[NPTS * NNEG];     // negative sample indices
__device__ float g_S[(size_t)NPTS * NPTS];    // 64MB ping
__device__ float g_T[(size_t)NPTS * NPTS];    // 64MB pong
__device__ double g_acc[8];               // 0:align 1:attr 2:rep 3:lap_cross 4:fro 5:diff

// ---------------- zero accumulators ----------------
__global__ void k_zero() {
    if (threadIdx.x < 8) g_acc[threadIdx.x] = 0.0;
}

// ---------------- normalize rows, collect raw atac norms + Frobenius ----------------
__global__ __launch_bounds__(128) void k_norm(const float* __restrict__ zr,
                                              const float* __restrict__ za) {
    int warp = threadIdx.x >> 5, lane = threadIdx.x & 31;
    int r = blockIdx.x * 4 + warp;
    float a0 = zr[r * DIM + lane],      a1 = zr[r * DIM + 32 + lane];
    float b0 = za[r * DIM + lane],      b1 = za[r * DIM + 32 + lane];
    float sr = a0 * a0 + a1 * a1;
    float sa = b0 * b0 + b1 * b1;
    #pragma unroll
    for (int o = 16; o; o >>= 1) {
        sr += __shfl_xor_sync(FULLMASK, sr, o);
        sa += __shfl_xor_sync(FULLMASK, sa, o);
    }
    float nr = fmaxf(sqrtf(sr), 1e-12f);
    float na = fmaxf(sqrtf(sa), 1e-12f);
    g_zr[r * DIM + lane]      = a0 / nr;
    g_zr[r * DIM + 32 + lane] = a1 / nr;
    g_za[r * DIM + lane]      = b0 / na;
    g_za[r * DIM + 32 + lane] = b1 / na;
    if (lane == 0) {
        g_anorm[r] = na;
        atomicAdd(&g_acc[4], (double)sa);   // Frobenius^2 of raw z_atac
    }
}

// ---------------- fused sim GEMM + per-row top-15 + softmax ----------------
// 32 queries per block, 8 key-slots per query (256 threads). Keys tiled via SMEM.
__global__ __launch_bounds__(256) void k_topk(int which) {
    const float* __restrict__ Zn = which ? g_za : g_zr;
    int*   __restrict__ oi = which ? g_ia : g_ir;
    float* __restrict__ ow = which ? g_wa : g_wr;

    __shared__ __align__(16) float pool[7680];
    float* Qs = pool;              // 32 rows, stride 68
    float* Ks = pool + 32 * 68;    // 64 rows, stride 68

    int tid = threadIdx.x;
    int qi = tid & 31, slot = tid >> 5;
    int qbase = blockIdx.x * 32;
    int q = qbase + qi;

    for (int e = tid; e < 32 * DIM; e += 256) {
        int rr = e >> 6, cc = e & 63;
        Qs[rr * 68 + cc] = Zn[(qbase + rr) * DIM + cc];
    }

    float tv[KNN]; int ti[KNN];
    #pragma unroll
    for (int u = 0; u < KNN; u++) { tv[u] = -1e30f; ti[u] = 0; }
    float vmin = -1e30f; int pmin = 0;

    const float4* Q4 = reinterpret_cast<const float4*>(Qs + qi * 68);

    for (int kt = 0; kt < 64; kt++) {
        __syncthreads();
        for (int e = tid; e < 64 * DIM; e += 256) {
            int rr = e >> 6, cc = e & 63;
            Ks[rr * 68 + cc] = Zn[(kt * 64 + rr) * DIM + cc];
        }
        __syncthreads();
        #pragma unroll
        for (int kk8 = 0; kk8 < 8; kk8++) {
            int kk = slot + kk8 * 8;
            int j = kt * 64 + kk;
            const float4* K4 = reinterpret_cast<const float4*>(Ks + kk * 68);
            float acc = 0.f;
            #pragma unroll
            for (int d = 0; d < 16; d++) {
                float4 a = Q4[d], b = K4[d];
                acc += a.x * b.x + a.y * b.y + a.z * b.z + a.w * b.w;
            }
            if (j != q && acc > vmin) {
                tv[pmin] = acc; ti[pmin] = j;
                vmin = tv[0]; pmin = 0;
                #pragma unroll
                for (int u = 1; u < KNN; u++)
                    if (tv[u] < vmin) { vmin = tv[u]; pmin = u; }
            }
        }
    }
    __syncthreads();

    // merge 8 per-slot top-15 lists per query
    float* cv = pool;                       // 32*120 floats
    int*   ci = (int*)(pool + 3840);        // 32*120 ints
    int base = qi * 120 + slot * KNN;
    #pragma unroll
    for (int u = 0; u < KNN; u++) { cv[base + u] = tv[u]; ci[base + u] = ti[u]; }
    __syncthreads();

    if (tid < 32) {
        float selv[KNN]; int seli[KNN];
        int cb = tid * 120;
        for (int s = 0; s < KNN; s++) {
            float bv = -2e30f; int bp = 0;
            for (int c = 0; c < 120; c++) {
                float v = cv[cb + c];
                if (v > bv) { bv = v; bp = c; }
            }
            selv[s] = bv; seli[s] = ci[cb + bp]; cv[cb + bp] = -3e30f;
        }
        float m = selv[0], sum = 0.f;
        float w[KNN];
        #pragma unroll
        for (int s = 0; s < KNN; s++) { w[s] = expf((selv[s] - m) * TEMP_INV); sum += w[s]; }
        float inv = 1.f / sum;
        int qq = qbase + tid;
        #pragma unroll
        for (int s = 0; s < KNN; s++) {
            oi[qq * KNN + s] = seli[s];
            ow[qq * KNN + s] = w[s] * inv;
        }
    }
}

// ---------------- negative sampling: top-32 of masked noise row (warp per row) ----------------
__global__ __launch_bounds__(64) void k_negs(const float* __restrict__ noise) {
    __shared__ __align__(16) float sv[2 * NPTS];
    int warp = threadIdx.x >> 5, lane = threadIdx.x & 31;
    int r = blockIdx.x * 2 + warp;
    float* row = sv + warp * NPTS;
    float4* row4 = (float4*)row;
    const float4* nr4 = (const float4*)(noise + (size_t)r * NPTS);
    #pragma unroll 4
    for (int k = 0; k < 32; k++) row4[lane + 32 * k] = nr4[lane + 32 * k];
    __syncwarp();
    if (lane == 0) row[r] = -1.0f;                       // diag
    if (lane < KNN) row[g_ir[r * KNN + lane]] = -1.0f;   // rna neighbors
    __syncwarp();

    float lv = -2e30f; int li = lane * 128;
    int b0 = lane * 128;
    for (int c = 0; c < 128; c++) {
        float v = row[b0 + c];
        if (v > lv) { lv = v; li = b0 + c; }
    }
    for (int m = 0; m < NNEG; m++) {
        float bv = lv; int bi = li;
        #pragma unroll
        for (int o = 16; o; o >>= 1) {
            float ov = __shfl_xor_sync(FULLMASK, bv, o);
            int   oj = __shfl_xor_sync(FULLMASK, bi, o);
            if (ov > bv || (ov == bv && oj < bi)) { bv = ov; bi = oj; }
        }
        if (lane == 0) g_ineg[r * NNEG + m] = bi;
        if ((bi >> 7) == lane) {      // owner re-scans
            row[bi] = -2e30f;
            lv = -2e30f; li = b0;
            for (int c = 0; c < 128; c++) {
                float v = row[b0 + c];
                if (v > lv) { lv = v; li = b0 + c; }
            }
        }
        __syncwarp();
    }
}

// ---------------- align-KL + attraction + repulsion + Laplacian cross (warp per row) ----------------
__global__ __launch_bounds__(128) void k_pair() {
    int warp = threadIdx.x >> 5, lane = threadIdx.x & 31;
    int r = blockIdx.x * 4 + warp;
    float q0 = g_za[r * DIM + lane], q1 = g_za[r * DIM + 32 + lane];
    int   irv = (lane < KNN) ? g_ir[r * KNN + lane] : 0;
    float wrv = (lane < KNN) ? g_wr[r * KNN + lane] : 0.f;
    int   iav = (lane < KNN) ? g_ia[r * KNN + lane] : -1;
    float wav = (lane < KNN) ? g_wa[r * KNN + lane] : 0.f;
    float anr = g_anorm[r];
    float align_s = 0.f, attr_s = 0.f, lap_s = 0.f, rep_s = 0.f;

    for (int t = 0; t < KNN; t++) {
        int   j  = __shfl_sync(FULLMASK, irv, t);
        float tw = __shfl_sync(FULLMASK, wrv, t);
        float d = q0 * g_za[j * DIM + lane] + q1 * g_za[j * DIM + 32 + lane];
        #pragma unroll
        for (int o = 16; o; o >>= 1) d += __shfl_xor_sync(FULLMASK, d, o);
        unsigned bl = __ballot_sync(FULLMASK, (lane < KNN) && (iav == j));
        float aeq = 0.f;
        if (bl) aeq = __shfl_sync(FULLMASK, wav, __ffs(bl) - 1);
        if (lane == 0) {
            attr_s  += 1.f - d;
            lap_s   += anr * g_anorm[j] * d;
            align_s += tw * (logf(tw) - logf(aeq + 1e-8f));
        }
    }
    for (int m = 0; m < NNEG; m++) {
        int j = g_ineg[r * NNEG + m];
        float d = q0 * g_za[j * DIM + lane] + q1 * g_za[j * DIM + 32 + lane];
        #pragma unroll
        for (int o = 16; o; o >>= 1) d += __shfl_xor_sync(FULLMASK, d, o);
        if (lane == 0) rep_s += fmaxf(MARGIN - (1.f - d), 0.f);
    }
    if (lane == 0) {
        atomicAdd(&g_acc[0], (double)align_s);
        atomicAdd(&g_acc[1], (double)(attr_s / (float)KNN));
        atomicAdd(&g_acc[2], (double)rep_s);
        atomicAdd(&g_acc[3], (double)lap_s);
    }
}

// ---------------- PPR step 1 done sparse-sparse: S1 = 0.8*A@A + 0.2*A  -> g_S ----------------
__global__ __launch_bounds__(256) void k_ppr_first() {
    __shared__ float srow[NPTS];
    __shared__ int sj[KNN]; __shared__ float sw[KNN];
    int r = blockIdx.x, tid = threadIdx.x;
    if (tid < KNN) { sj[tid] = g_ir[r * KNN + tid]; sw[tid] = g_wr[r * KNN + tid]; }
    float4* sr4 = (float4*)srow;
    float4 z = {0.f, 0.f, 0.f, 0.f};
    #pragma unroll
    for (int k = 0; k < 4; k++) sr4[tid + 256 * k] = z;
    __syncthreads();
    if (tid < KNN * KNN) {
        int t = tid / KNN, u = tid % KNN;
        int j = sj[t];
        atomicAdd(&srow[g_ir[j * KNN + u]], 0.8f * sw[t] * g_wr[j * KNN + u]);
    }
    if (tid < KNN) atomicAdd(&srow[sj[tid]], 0.2f * sw[tid]);
    __syncthreads();
    float4* d4 = (float4*)(g_S + (size_t)r * NPTS);
    #pragma unroll
    for (int k = 0; k < 4; k++) d4[tid + 256 * k] = sr4[tid + 256 * k];
}

// ---------------- dense PPR iteration: dst = 0.8*A@src + 0.2*A ----------------
__global__ __launch_bounds__(256) void k_ppr_iter(int it) {
    const float* __restrict__ src = (it & 1) ? g_T : g_S;
    float* __restrict__ dst       = (it & 1) ? g_S : g_T;
    int r = blockIdx.x, tid = threadIdx.x;
    __shared__ int sj[KNN]; __shared__ float sw[KNN];
    if (tid < KNN) { sj[tid] = g_ir[r * KNN + tid]; sw[tid] = g_wr[r * KNN + tid]; }
    __syncthreads();
    int rj[KNN]; float rw[KNN];
    #pragma unroll
    for (int t = 0; t < KNN; t++) { rj[t] = sj[t]; rw[t] = sw[t]; }

    const float4* s4 = (const float4*)src;
    float4* d4 = (float4*)(dst + (size_t)r * NPTS);
    #pragma unroll
    for (int k = 0; k < 4; k++) {
        int c = tid + 256 * k;
        float ax = 0.f, ay = 0.f, az = 0.f, aw = 0.f;
        #pragma unroll
        for (int t = 0; t < KNN; t++) {
            float4 v = s4[(size_t)rj[t] * (NPTS / 4) + c];
            float w = rw[t];
            ax += w * v.x; ay += w * v.y; az += w * v.z; aw += w * v.w;
        }
        float4 o; o.x = 0.8f * ax; o.y = 0.8f * ay; o.z = 0.8f * az; o.w = 0.8f * aw;
        d4[c] = o;
    }
    __syncthreads();
    if (tid < KNN) dst[(size_t)r * NPTS + sj[tid]] += 0.2f * sw[tid];
}

// ---------------- row-normalize S and accumulate diff = sum (A_atac - S_hat)^2 ----------------
__global__ __launch_bounds__(256) void k_ppr_final() {
    const float* __restrict__ S = g_S;   // after 4 dense iters, final lives in g_S
    int r = blockIdx.x, tid = threadIdx.x;
    const float4* s4 = (const float4*)(S + (size_t)r * NPTS);
    float sum = 0.f, sq = 0.f;
    #pragma unroll
    for (int k = 0; k < 4; k++) {
        float4 v = s4[tid + 256 * k];
        sum += v.x + v.y + v.z + v.w;
        sq  += v.x * v.x + v.y * v.y + v.z * v.z + v.w * v.w;
    }
    __shared__ float s1[256], s2[256];
    s1[tid] = sum; s2[tid] = sq;
    __syncthreads();
    for (int o = 128; o; o >>= 1) {
        if (tid < o) { s1[tid] += s1[tid + o]; s2[tid] += s2[tid + o]; }
        __syncthreads();
    }
    if (tid == 0) {
        float rs = s1[0], rq = s2[0];
        float rinv = 1.f / fmaxf(rs, 1e-8f);
        float cross = 0.f, a2 = 0.f;
        for (int t = 0; t < KNN; t++) {
            int c = g_ia[r * KNN + t];
            float a = g_wa[r * KNN + t];
            cross += a * S[(size_t)r * NPTS + c];
            a2 += a * a;
        }
        double rowdiff = (double)rq * rinv * rinv - 2.0 * (double)rinv * (double)cross + (double)a2;
        atomicAdd(&g_acc[5], rowdiff);
    }
}

// ---------------- combine ----------------
__global__ void k_final(float* out) {
    double align = g_acc[0] / 4096.0;
    double attr  = g_acc[1] / 4096.0;
    double rep   = g_acc[2] / (4096.0 * 32.0);
    double lap   = (g_acc[4] - g_acc[3] / 15.0) / 4096.0;
    double diff  = g_acc[5] / (4096.0 * 4096.0);
    out[0] = (float)(align + (attr + rep) + 0.5 * lap + 0.5 * diff);
}

extern "C" void kernel_launch(void* const* d_in, const int* in_sizes, int n_in,
                              void* d_out, int out_size) {
    (void)in_sizes; (void)n_in; (void)out_size;
    const float* zr    = (const float*)d_in[0];
    const float* za    = (const float*)d_in[1];
    const float* noise = (const float*)d_in[2];
    float* out = (float*)d_out;

    k_zero<<<1, 32>>>();
    k_norm<<<NPTS / 4, 128>>>(zr, za);
    k_topk<<<NPTS / 32, 256>>>(0);   // rna graph
    k_topk<<<NPTS / 32, 256>>>(1);   // atac graph
    k_negs<<<NPTS / 2, 64>>>(noise);
    k_pair<<<NPTS / 4, 128>>>();
    k_ppr_first<<<NPTS, 256>>>();               // S1 -> g_S
    for (int it = 0; it < 4; it++)              // S2..S5
        k_ppr_iter<<<NPTS, 256>>>(it);          // final -> g_S
    k_ppr_final<<<NPTS, 256>>>();
    k_final<<<1, 1>>>(out);
}

// round 5
// speedup vs baseline: 1.4347x; 1.4347x over previous
#include <cuda_runtime.h>
#include <cuda_fp16.h>
#include <math.h>

#define NPTS 4096
#define DIM  64
#define KNN  15
#define NNEG 32
#define TEMP_INV 10.0f
#define MARGIN 0.5f
#define FULLMASK 0xffffffffu

// ---------------- device scratch (allocation-free per rules) ----------------
__device__ float g_zr[NPTS * DIM];        // normalized z_rna
__device__ float g_za[NPTS * DIM];        // normalized z_atac
__device__ float g_anorm[NPTS];           // raw ||z_atac_i||
__device__ int   g_ir[NPTS * KNN];        // rna knn indices
__device__ float g_wr[NPTS * KNN];        // rna softmax weights
__device__ int   g_ia[NPTS * KNN];        // atac knn indices
__device__ float g_wa[NPTS * KNN];        // atac softmax weights
__device__ int   g_ineg[NPTS * NNEG];     // negative sample indices
__device__ __half g_Sh[(size_t)NPTS * NPTS];  // 32MB ping (fp16 S)
__device__ __half g_Th[(size_t)NPTS * NPTS];  // 32MB pong
__device__ double g_acc[8];               // 0:align 1:attr 2:rep 3:lap_cross 4:fro 5:diff

// ---------------- zero accumulators ----------------
__global__ void k_zero() {
    if (threadIdx.x < 8) g_acc[threadIdx.x] = 0.0;
}

// ---------------- normalize rows, collect raw atac norms + Frobenius ----------------
__global__ __launch_bounds__(128) void k_norm(const float* __restrict__ zr,
                                              const float* __restrict__ za) {
    int warp = threadIdx.x >> 5, lane = threadIdx.x & 31;
    int r = blockIdx.x * 4 + warp;
    float a0 = zr[r * DIM + lane],      a1 = zr[r * DIM + 32 + lane];
    float b0 = za[r * DIM + lane],      b1 = za[r * DIM + 32 + lane];
    float sr = a0 * a0 + a1 * a1;
    float sa = b0 * b0 + b1 * b1;
    #pragma unroll
    for (int o = 16; o; o >>= 1) {
        sr += __shfl_xor_sync(FULLMASK, sr, o);
        sa += __shfl_xor_sync(FULLMASK, sa, o);
    }
    float nr = fmaxf(sqrtf(sr), 1e-12f);
    float na = fmaxf(sqrtf(sa), 1e-12f);
    g_zr[r * DIM + lane]      = a0 / nr;
    g_zr[r * DIM + 32 + lane] = a1 / nr;
    g_za[r * DIM + lane]      = b0 / na;
    g_za[r * DIM + 32 + lane] = b1 / na;
    if (lane == 0) {
        g_anorm[r] = na;
        atomicAdd(&g_acc[4], (double)sa);   // Frobenius^2 of raw z_atac
    }
}

// ---------------- register-tiled sim GEMM + top-15 + softmax, both graphs ----------------
// Block: 256 threads (16x16). 64 queries/block, key tiles of 128.
// Thread (ty,tx): 4 queries (ty*4..+3) x 8 keys ({4tx..4tx+3} and {64+4tx..+3}).
// SMEM tiles stored d-major (transposed) with XOR swizzle for conflict-free LDS.128.
#define QSTR 68    // Qt row stride in floats (17 granules)
#define KSTR 132   // Kt/Sc row stride in floats (33 granules)

__global__ __launch_bounds__(256, 2) void k_topk2() {
    extern __shared__ __align__(16) float smem[];
    float* Qt = smem;                    // 64 * 68  = 4352 floats
    float* Kt = smem + 64 * QSTR;        // 64 * 132 = 8448 floats
    float* Sc = Kt + 64 * KSTR;          // 64 * 132 = 8448 floats
    float4* Qt4 = (float4*)Qt;
    float4* Kt4 = (float4*)Kt;
    float4* Sc4 = (float4*)Sc;

    int which = blockIdx.y;
    const float* __restrict__ Zn = which ? g_za : g_zr;
    int*   __restrict__ oi = which ? g_ia : g_ir;
    float* __restrict__ ow = which ? g_wa : g_wr;
    const float4* Zn4 = (const float4*)Zn;

    int tid = threadIdx.x;
    int tx = tid & 15, ty = tid >> 4;
    int qbase = blockIdx.x * 64;
    int q_loc = tid >> 2, part = tid & 3;
    int q_self = qbase + q_loc;

    // ---- load + transpose Q tile (64 q x 64 d), swizzled ----
    #pragma unroll
    for (int l = 0; l < 4; l++) {
        int idx = tid + l * 256;
        int q = idx >> 4, d4 = idx & 15;
        float4 v = Zn4[(qbase + q) * 16 + d4];
        int qg = q >> 2, qr = q & 3;
        int sw = d4 & 7;
        int base = ((qg ^ sw) << 2) + qr;
        Qt[(4 * d4 + 0) * QSTR + base] = v.x;
        Qt[(4 * d4 + 1) * QSTR + base] = v.y;
        Qt[(4 * d4 + 2) * QSTR + base] = v.z;
        Qt[(4 * d4 + 3) * QSTR + base] = v.w;
    }

    float tv[KNN]; int ti[KNN];
    #pragma unroll
    for (int u = 0; u < KNN; u++) { tv[u] = -1e30f; ti[u] = 0; }
    float vmin = -1e30f; int pmin = 0;

    for (int kt = 0; kt < 32; kt++) {
        int kbase = kt * 128;
        __syncthreads();   // prev insert done; safe to overwrite Kt
        // ---- load + transpose K tile (128 k x 64 d), swizzled ----
        #pragma unroll
        for (int l = 0; l < 8; l++) {
            int idx = tid + l * 256;
            int k = idx >> 4, d4 = idx & 15;
            float4 v = Zn4[(kbase + k) * 16 + d4];
            int kg = k >> 2, kr = k & 3;
            int sw = d4 & 7;
            int base = ((kg ^ sw) << 2) + kr;
            Kt[(4 * d4 + 0) * KSTR + base] = v.x;
            Kt[(4 * d4 + 1) * KSTR + base] = v.y;
            Kt[(4 * d4 + 2) * KSTR + base] = v.z;
            Kt[(4 * d4 + 3) * KSTR + base] = v.w;
        }
        __syncthreads();

        // ---- compute 4x8 register tile ----
        float acc[4][8];
        #pragma unroll
        for (int i = 0; i < 4; i++)
            #pragma unroll
            for (int j = 0; j < 8; j++) acc[i][j] = 0.f;

        #pragma unroll 4
        for (int d = 0; d < 64; d++) {
            int w = (d >> 2) & 7;
            float4 a  = Qt4[d * 17 + (ty ^ w)];
            float4 b0 = Kt4[d * 33 + (tx ^ w)];
            float4 b1 = Kt4[d * 33 + 16 + (tx ^ w)];
            float av[4] = {a.x, a.y, a.z, a.w};
            float bv[8] = {b0.x, b0.y, b0.z, b0.w, b1.x, b1.y, b1.z, b1.w};
            #pragma unroll
            for (int i = 0; i < 4; i++)
                #pragma unroll
                for (int j = 0; j < 8; j++)
                    acc[i][j] = fmaf(av[i], bv[j], acc[i][j]);
        }

        // ---- write score tile ----
        #pragma unroll
        for (int i = 0; i < 4; i++) {
            float4 s0; s0.x = acc[i][0]; s0.y = acc[i][1]; s0.z = acc[i][2]; s0.w = acc[i][3];
            float4 s1; s1.x = acc[i][4]; s1.y = acc[i][5]; s1.z = acc[i][6]; s1.w = acc[i][7];
            Sc4[(ty * 4 + i) * 33 + tx]      = s0;
            Sc4[(ty * 4 + i) * 33 + 16 + tx] = s1;
        }
        __syncthreads();

        // ---- insert: 4 threads/query, each scans 32 cols (bank-staggered) ----
        int rowb = q_loc * KSTR + part * 32;
        int colb = kbase + part * 32;
        #pragma unroll 4
        for (int c0 = 0; c0 < 32; c0++) {
            int c = (c0 + part * 8) & 31;
            float v = Sc[rowb + c];
            int jg = colb + c;
            if (jg != q_self && v > vmin) {
                tv[pmin] = v; ti[pmin] = jg;
                vmin = tv[0]; pmin = 0;
                #pragma unroll
                for (int u = 1; u < KNN; u++)
                    if (tv[u] < vmin) { vmin = tv[u]; pmin = u; }
            }
        }
    }
    __syncthreads();

    // ---- merge 4 per-part lists (60 candidates/query), softmax, write ----
    float* candv = smem;                      // overlays Qt (needs 3840 floats)
    int*   candi = (int*)(smem + 64 * QSTR);  // overlays Kt
    int cb = q_loc * 60 + part * KNN;
    #pragma unroll
    for (int u = 0; u < KNN; u++) { candv[cb + u] = tv[u]; candi[cb + u] = ti[u]; }
    __syncthreads();

    if (tid < 64) {
        int b = tid * 60;
        float selv[KNN]; int seli[KNN];
        for (int s = 0; s < KNN; s++) {
            float bv = -2e30f; int bp = 0;
            for (int c = 0; c < 60; c++) {
                float v = candv[b + c];
                if (v > bv) { bv = v; bp = c; }
            }
            selv[s] = bv; seli[s] = candi[b + bp]; candv[b + bp] = -3e30f;
        }
        float m = selv[0], sum = 0.f;
        float wv[KNN];
        #pragma unroll
        for (int s = 0; s < KNN; s++) { wv[s] = expf((selv[s] - m) * TEMP_INV); sum += wv[s]; }
        float inv = 1.f / sum;
        int qq = qbase + tid;
        #pragma unroll
        for (int s = 0; s < KNN; s++) {
            oi[qq * KNN + s] = seli[s];
            ow[qq * KNN + s] = wv[s] * inv;
        }
    }
}

// ---------------- negative sampling: top-32 of masked noise row (warp per row) ----------------
__global__ __launch_bounds__(64) void k_negs(const float* __restrict__ noise) {
    __shared__ __align__(16) float sv[2 * NPTS];
    int warp = threadIdx.x >> 5, lane = threadIdx.x & 31;
    int r = blockIdx.x * 2 + warp;
    float* row = sv + warp * NPTS;
    float4* row4 = (float4*)row;
    const float4* nr4 = (const float4*)(noise + (size_t)r * NPTS);
    #pragma unroll 4
    for (int k = 0; k < 32; k++) row4[lane + 32 * k] = nr4[lane + 32 * k];
    __syncwarp();
    if (lane == 0) row[r] = -1.0f;                       // diag
    if (lane < KNN) row[g_ir[r * KNN + lane]] = -1.0f;   // rna neighbors
    __syncwarp();

    float lv = -2e30f; int li = lane * 128;
    int b0 = lane * 128;
    for (int c = 0; c < 128; c++) {
        float v = row[b0 + c];
        if (v > lv) { lv = v; li = b0 + c; }
    }
    for (int m = 0; m < NNEG; m++) {
        float bv = lv; int bi = li;
        #pragma unroll
        for (int o = 16; o; o >>= 1) {
            float ov = __shfl_xor_sync(FULLMASK, bv, o);
            int   oj = __shfl_xor_sync(FULLMASK, bi, o);
            if (ov > bv || (ov == bv && oj < bi)) { bv = ov; bi = oj; }
        }
        if (lane == 0) g_ineg[r * NNEG + m] = bi;
        if ((bi >> 7) == lane) {      // owner re-scans
            row[bi] = -2e30f;
            lv = -2e30f; li = b0;
            for (int c = 0; c < 128; c++) {
                float v = row[b0 + c];
                if (v > lv) { lv = v; li = b0 + c; }
            }
        }
        __syncwarp();
    }
}

// ---------------- align-KL + attraction + repulsion + Laplacian cross (warp per row) ----------------
__global__ __launch_bounds__(128) void k_pair() {
    int warp = threadIdx.x >> 5, lane = threadIdx.x & 31;
    int r = blockIdx.x * 4 + warp;
    float q0 = g_za[r * DIM + lane], q1 = g_za[r * DIM + 32 + lane];
    int   irv = (lane < KNN) ? g_ir[r * KNN + lane] : 0;
    float wrv = (lane < KNN) ? g_wr[r * KNN + lane] : 0.f;
    int   iav = (lane < KNN) ? g_ia[r * KNN + lane] : -1;
    float wav = (lane < KNN) ? g_wa[r * KNN + lane] : 0.f;
    float anr = g_anorm[r];
    float align_s = 0.f, attr_s = 0.f, lap_s = 0.f, rep_s = 0.f;

    for (int t = 0; t < KNN; t++) {
        int   j  = __shfl_sync(FULLMASK, irv, t);
        float tw = __shfl_sync(FULLMASK, wrv, t);
        float d = q0 * g_za[j * DIM + lane] + q1 * g_za[j * DIM + 32 + lane];
        #pragma unroll
        for (int o = 16; o; o >>= 1) d += __shfl_xor_sync(FULLMASK, d, o);
        unsigned bl = __ballot_sync(FULLMASK, (lane < KNN) && (iav == j));
        float aeq = 0.f;
        if (bl) aeq = __shfl_sync(FULLMASK, wav, __ffs(bl) - 1);
        if (lane == 0) {
            attr_s  += 1.f - d;
            lap_s   += anr * g_anorm[j] * d;
            align_s += tw * (logf(tw) - logf(aeq + 1e-8f));
        }
    }
    for (int m = 0; m < NNEG; m++) {
        int j = g_ineg[r * NNEG + m];
        float d = q0 * g_za[j * DIM + lane] + q1 * g_za[j * DIM + 32 + lane];
        #pragma unroll
        for (int o = 16; o; o >>= 1) d += __shfl_xor_sync(FULLMASK, d, o);
        if (lane == 0) rep_s += fmaxf(MARGIN - (1.f - d), 0.f);
    }
    if (lane == 0) {
        atomicAdd(&g_acc[0], (double)align_s);
        atomicAdd(&g_acc[1], (double)(attr_s / (float)KNN));
        atomicAdd(&g_acc[2], (double)rep_s);
        atomicAdd(&g_acc[3], (double)lap_s);
    }
}

// ---------------- PPR step 1 sparse-sparse: S1 = 0.8*A@A + 0.2*A  -> g_Sh (fp16) ----------------
__global__ __launch_bounds__(256) void k_ppr_first() {
    __shared__ float srow[NPTS];
    __shared__ int sj[KNN]; __shared__ float sw_[KNN];
    int r = blockIdx.x, tid = threadIdx.x;
    if (tid < KNN) { sj[tid] = g_ir[r * KNN + tid]; sw_[tid] = g_wr[r * KNN + tid]; }
    float4* sr4 = (float4*)srow;
    float4 z = {0.f, 0.f, 0.f, 0.f};
    #pragma unroll
    for (int k = 0; k < 4; k++) sr4[tid + 256 * k] = z;
    __syncthreads();
    if (tid < KNN * KNN) {
        int t = tid / KNN, u = tid % KNN;
        int j = sj[t];
        atomicAdd(&srow[g_ir[j * KNN + u]], 0.8f * sw_[t] * g_wr[j * KNN + u]);
    }
    if (tid < KNN) atomicAdd(&srow[sj[tid]], 0.2f * sw_[tid]);
    __syncthreads();
    __half2* dh = (__half2*)(g_Sh + (size_t)r * NPTS);
    #pragma unroll
    for (int k = 0; k < 8; k++) {
        int i = tid + 256 * k;
        dh[i] = __floats2half2_rn(srow[2 * i], srow[2 * i + 1]);
    }
}

// ---------------- dense PPR iteration (fp16 S, fp32 accumulate): dst = 0.8*A@src + 0.2*A ----------------
__global__ __launch_bounds__(256) void k_ppr_iter(int it) {
    const __half* __restrict__ src = (it & 1) ? g_Th : g_Sh;
    __half* __restrict__ dst       = (it & 1) ? g_Sh : g_Th;
    int r = blockIdx.x, tid = threadIdx.x;
    __shared__ int sj[KNN]; __shared__ float sw_[KNN];
    if (tid < KNN) { sj[tid] = g_ir[r * KNN + tid]; sw_[tid] = g_wr[r * KNN + tid]; }
    __syncthreads();
    int rj[KNN]; float rw[KNN];
    #pragma unroll
    for (int t = 0; t < KNN; t++) { rj[t] = sj[t]; rw[t] = sw_[t]; }

    const uint4* s4 = (const uint4*)src;             // 8 halves per uint4; 512/row
    uint4* d4p = (uint4*)(dst + (size_t)r * NPTS);
    #pragma unroll
    for (int g = 0; g < 2; g++) {
        int c = tid + 256 * g;
        float a[8];
        #pragma unroll
        for (int e = 0; e < 8; e++) a[e] = 0.f;
        #pragma unroll
        for (int t = 0; t < KNN; t++) {
            uint4 v = s4[(size_t)rj[t] * 512 + c];
            float w = rw[t];
            float2 f0 = __half22float2(*(__half2*)&v.x);
            float2 f1 = __half22float2(*(__half2*)&v.y);
            float2 f2 = __half22float2(*(__half2*)&v.z);
            float2 f3 = __half22float2(*(__half2*)&v.w);
            a[0] += w * f0.x; a[1] += w * f0.y;
            a[2] += w * f1.x; a[3] += w * f1.y;
            a[4] += w * f2.x; a[5] += w * f2.y;
            a[6] += w * f3.x; a[7] += w * f3.y;
        }
        __half2 o0 = __floats2half2_rn(0.8f * a[0], 0.8f * a[1]);
        __half2 o1 = __floats2half2_rn(0.8f * a[2], 0.8f * a[3]);
        __half2 o2 = __floats2half2_rn(0.8f * a[4], 0.8f * a[5]);
        __half2 o3 = __floats2half2_rn(0.8f * a[6], 0.8f * a[7]);
        uint4 ov;
        ov.x = *(unsigned*)&o0; ov.y = *(unsigned*)&o1;
        ov.z = *(unsigned*)&o2; ov.w = *(unsigned*)&o3;
        d4p[c] = ov;
    }
    __syncthreads();
    if (tid < KNN) {
        size_t p = (size_t)r * NPTS + sj[tid];
        dst[p] = __float2half(__half2float(dst[p]) + 0.2f * sw_[tid]);
    }
}

// ---------------- row-normalize S and accumulate diff = sum (A_atac - S_hat)^2 ----------------
__global__ __launch_bounds__(256) void k_ppr_final() {
    const __half* __restrict__ S = g_Sh;   // after 4 dense iters, final lives in g_Sh
    int r = blockIdx.x, tid = threadIdx.x;
    const uint4* s4 = (const uint4*)(S + (size_t)r * NPTS);
    float sum = 0.f, sq = 0.f;
    #pragma unroll
    for (int g = 0; g < 2; g++) {
        uint4 v = s4[tid + 256 * g];
        float2 f0 = __half22float2(*(__half2*)&v.x);
        float2 f1 = __half22float2(*(__half2*)&v.y);
        float2 f2 = __half22float2(*(__half2*)&v.z);
        float2 f3 = __half22float2(*(__half2*)&v.w);
        sum += f0.x + f0.y + f1.x + f1.y + f2.x + f2.y + f3.x + f3.y;
        sq  += f0.x*f0.x + f0.y*f0.y + f1.x*f1.x + f1.y*f1.y
             + f2.x*f2.x + f2.y*f2.y + f3.x*f3.x + f3.y*f3.y;
    }
    __shared__ float s1[256], s2[256];
    s1[tid] = sum; s2[tid] = sq;
    __syncthreads();
    for (int o = 128; o; o >>= 1) {
        if (tid < o) { s1[tid] += s1[tid + o]; s2[tid] += s2[tid + o]; }
        __syncthreads();
    }
    if (tid == 0) {
        float rs = s1[0], rq = s2[0];
        float rinv = 1.f / fmaxf(rs, 1e-8f);
        float cross = 0.f, a2 = 0.f;
        for (int t = 0; t < KNN; t++) {
            int c = g_ia[r * KNN + t];
            float a = g_wa[r * KNN + t];
            cross += a * __half2float(S[(size_t)r * NPTS + c]);
            a2 += a * a;
        }
        double rowdiff = (double)rq * rinv * rinv - 2.0 * (double)rinv * (double)cross + (double)a2;
        atomicAdd(&g_acc[5], rowdiff);
    }
}

// ---------------- combine ----------------
__global__ void k_final(float* out) {
    double align = g_acc[0] / 4096.0;
    double attr  = g_acc[1] / 4096.0;
    double rep   = g_acc[2] / (4096.0 * 32.0);
    double lap   = (g_acc[4] - g_acc[3] / 15.0) / 4096.0;
    double diff  = g_acc[5] / (4096.0 * 4096.0);
    out[0] = (float)(align + (attr + rep) + 0.5 * lap + 0.5 * diff);
}

extern "C" void kernel_launch(void* const* d_in, const int* in_sizes, int n_in,
                              void* d_out, int out_size) {
    (void)in_sizes; (void)n_in; (void)out_size;
    const float* zr    = (const float*)d_in[0];
    const float* za    = (const float*)d_in[1];
    const float* noise = (const float*)d_in[2];
    float* out = (float*)d_out;

    const int SMEM_TOPK = (64 * QSTR + 64 * KSTR + 64 * KSTR) * (int)sizeof(float); // 84992 B
    cudaFuncSetAttribute(k_topk2, cudaFuncAttributeMaxDynamicSharedMemorySize, SMEM_TOPK);

    k_zero<<<1, 32>>>();
    k_norm<<<NPTS / 4, 128>>>(zr, za);
    k_topk2<<<dim3(64, 2), 256, SMEM_TOPK>>>();   // both graphs fused
    k_negs<<<NPTS / 2, 64>>>(noise);
    k_pair<<<NPTS / 4, 128>>>();
    k_ppr_first<<<NPTS, 256>>>();                 // S1 -> g_Sh
    for (int it = 0; it < 4; it++)                // S2..S5
        k_ppr_iter<<<NPTS, 256>>>(it);            // final -> g_Sh
    k_ppr_final<<<NPTS, 256>>>();
    k_final<<<1, 1>>>(out);
}

// round 6
// speedup vs baseline: 1.6847x; 1.1742x over previous
#include <cuda_runtime.h>
#include <cuda_fp16.h>
#include <cuda_fp8.h>
#include <math.h>

#define NPTS 4096
#define DIM  64
#define KNN  15
#define NNEG 32
#define TEMP_INV 10.0f
#define MARGIN 0.5f
#define FULLMASK 0xffffffffu
#define NEG_THRESH 0.98f
#define PPR_SCALE 64.0f

// ---------------- device scratch (allocation-free per rules) ----------------
__device__ float g_zr[NPTS * DIM];        // normalized z_rna
__device__ float g_za[NPTS * DIM];        // normalized z_atac
__device__ float g_anorm[NPTS];           // raw ||z_atac_i||
__device__ int   g_ir[NPTS * KNN];        // rna knn indices
__device__ float g_wr[NPTS * KNN];        // rna softmax weights
__device__ int   g_ia[NPTS * KNN];        // atac knn indices
__device__ float g_wa[NPTS * KNN];        // atac softmax weights
__device__ int   g_ineg[NPTS * NNEG];     // negative sample indices
__device__ unsigned char g_S8[(size_t)NPTS * NPTS];  // 16MB ping (fp8 e4m3, stores 64*S)
__device__ unsigned char g_T8[(size_t)NPTS * NPTS];  // 16MB pong
__device__ double g_acc[8];               // 0:align 1:attr 2:rep 3:lap_cross 4:fro 5:diff

// ---------------- zero accumulators ----------------
__global__ void k_zero() {
    if (threadIdx.x < 8) g_acc[threadIdx.x] = 0.0;
}

// ---------------- normalize rows, collect raw atac norms + Frobenius ----------------
__global__ __launch_bounds__(128) void k_norm(const float* __restrict__ zr,
                                              const float* __restrict__ za) {
    int warp = threadIdx.x >> 5, lane = threadIdx.x & 31;
    int r = blockIdx.x * 4 + warp;
    float a0 = zr[r * DIM + lane],      a1 = zr[r * DIM + 32 + lane];
    float b0 = za[r * DIM + lane],      b1 = za[r * DIM + 32 + lane];
    float sr = a0 * a0 + a1 * a1;
    float sa = b0 * b0 + b1 * b1;
    #pragma unroll
    for (int o = 16; o; o >>= 1) {
        sr += __shfl_xor_sync(FULLMASK, sr, o);
        sa += __shfl_xor_sync(FULLMASK, sa, o);
    }
    float nr = fmaxf(sqrtf(sr), 1e-12f);
    float na = fmaxf(sqrtf(sa), 1e-12f);
    g_zr[r * DIM + lane]      = a0 / nr;
    g_zr[r * DIM + 32 + lane] = a1 / nr;
    g_za[r * DIM + lane]      = b0 / na;
    g_za[r * DIM + 32 + lane] = b1 / na;
    if (lane == 0) {
        g_anorm[r] = na;
        atomicAdd(&g_acc[4], (double)sa);   // Frobenius^2 of raw z_atac
    }
}

// ---------------- register-tiled sim GEMM + top-15 + softmax, both graphs ----------------
#define QSTR 68    // Qt row stride in floats (17 granules)
#define KSTR 132   // Kt/Sc row stride in floats (33 granules)

__global__ __launch_bounds__(256, 2) void k_topk2() {
    extern __shared__ __align__(16) float smem[];
    float* Qt = smem;                    // 64 * 68  = 4352 floats
    float* Kt = smem + 64 * QSTR;        // 64 * 132 = 8448 floats
    float* Sc = Kt + 64 * KSTR;          // 64 * 132 = 8448 floats
    float4* Qt4 = (float4*)Qt;
    float4* Kt4 = (float4*)Kt;
    float4* Sc4 = (float4*)Sc;

    int which = blockIdx.y;
    const float* __restrict__ Zn = which ? g_za : g_zr;
    int*   __restrict__ oi = which ? g_ia : g_ir;
    float* __restrict__ ow = which ? g_wa : g_wr;
    const float4* Zn4 = (const float4*)Zn;

    int tid = threadIdx.x;
    int tx = tid & 15, ty = tid >> 4;
    int qbase = blockIdx.x * 64;
    int q_loc = tid >> 2, part = tid & 3;
    int q_self = qbase + q_loc;

    // ---- load + transpose Q tile (64 q x 64 d), swizzled ----
    #pragma unroll
    for (int l = 0; l < 4; l++) {
        int idx = tid + l * 256;
        int q = idx >> 4, d4 = idx & 15;
        float4 v = Zn4[(qbase + q) * 16 + d4];
        int qg = q >> 2, qr = q & 3;
        int sw = d4 & 7;
        int base = ((qg ^ sw) << 2) + qr;
        Qt[(4 * d4 + 0) * QSTR + base] = v.x;
        Qt[(4 * d4 + 1) * QSTR + base] = v.y;
        Qt[(4 * d4 + 2) * QSTR + base] = v.z;
        Qt[(4 * d4 + 3) * QSTR + base] = v.w;
    }

    float tv[KNN]; int ti[KNN];
    #pragma unroll
    for (int u = 0; u < KNN; u++) { tv[u] = -1e30f; ti[u] = 0; }
    float vmin = -1e30f; int pmin = 0;

    for (int kt = 0; kt < 32; kt++) {
        int kbase = kt * 128;
        __syncthreads();   // prev insert done; safe to overwrite Kt
        // ---- load + transpose K tile (128 k x 64 d), swizzled ----
        #pragma unroll
        for (int l = 0; l < 8; l++) {
            int idx = tid + l * 256;
            int k = idx >> 4, d4 = idx & 15;
            float4 v = Zn4[(kbase + k) * 16 + d4];
            int kg = k >> 2, kr = k & 3;
            int sw = d4 & 7;
            int base = ((kg ^ sw) << 2) + kr;
            Kt[(4 * d4 + 0) * KSTR + base] = v.x;
            Kt[(4 * d4 + 1) * KSTR + base] = v.y;
            Kt[(4 * d4 + 2) * KSTR + base] = v.z;
            Kt[(4 * d4 + 3) * KSTR + base] = v.w;
        }
        __syncthreads();

        // ---- compute 4x8 register tile ----
        float acc[4][8];
        #pragma unroll
        for (int i = 0; i < 4; i++)
            #pragma unroll
            for (int j = 0; j < 8; j++) acc[i][j] = 0.f;

        #pragma unroll 4
        for (int d = 0; d < 64; d++) {
            int w = (d >> 2) & 7;
            float4 a  = Qt4[d * 17 + (ty ^ w)];
            float4 b0 = Kt4[d * 33 + (tx ^ w)];
            float4 b1 = Kt4[d * 33 + 16 + (tx ^ w)];
            float av[4] = {a.x, a.y, a.z, a.w};
            float bv[8] = {b0.x, b0.y, b0.z, b0.w, b1.x, b1.y, b1.z, b1.w};
            #pragma unroll
            for (int i = 0; i < 4; i++)
                #pragma unroll
                for (int j = 0; j < 8; j++)
                    acc[i][j] = fmaf(av[i], bv[j], acc[i][j]);
        }

        // ---- write score tile ----
        #pragma unroll
        for (int i = 0; i < 4; i++) {
            float4 s0; s0.x = acc[i][0]; s0.y = acc[i][1]; s0.z = acc[i][2]; s0.w = acc[i][3];
            float4 s1; s1.x = acc[i][4]; s1.y = acc[i][5]; s1.z = acc[i][6]; s1.w = acc[i][7];
            Sc4[(ty * 4 + i) * 33 + tx]      = s0;
            Sc4[(ty * 4 + i) * 33 + 16 + tx] = s1;
        }
        __syncthreads();

        // ---- insert: 4 threads/query, each scans 32 cols (bank-staggered) ----
        int rowb = q_loc * KSTR + part * 32;
        int colb = kbase + part * 32;
        #pragma unroll 4
        for (int c0 = 0; c0 < 32; c0++) {
            int c = (c0 + part * 8) & 31;
            float v = Sc[rowb + c];
            int jg = colb + c;
            if (jg != q_self && v > vmin) {
                tv[pmin] = v; ti[pmin] = jg;
                vmin = tv[0]; pmin = 0;
                #pragma unroll
                for (int u = 1; u < KNN; u++)
                    if (tv[u] < vmin) { vmin = tv[u]; pmin = u; }
            }
        }
    }
    __syncthreads();

    // ---- merge 4 per-part lists (60 candidates/query), softmax, write ----
    float* candv = smem;                      // overlays Qt
    int*   candi = (int*)(smem + 64 * QSTR);  // overlays Kt
    int cb = q_loc * 60 + part * KNN;
    #pragma unroll
    for (int u = 0; u < KNN; u++) { candv[cb + u] = tv[u]; candi[cb + u] = ti[u]; }
    __syncthreads();

    if (tid < 64) {
        int b = tid * 60;
        float selv[KNN]; int seli[KNN];
        for (int s = 0; s < KNN; s++) {
            float bv = -2e30f; int bp = 0;
            for (int c = 0; c < 60; c++) {
                float v = candv[b + c];
                if (v > bv) { bv = v; bp = c; }
            }
            selv[s] = bv; seli[s] = candi[b + bp]; candv[b + bp] = -3e30f;
        }
        float m = selv[0], sum = 0.f;
        float wv[KNN];
        #pragma unroll
        for (int s = 0; s < KNN; s++) { wv[s] = expf((selv[s] - m) * TEMP_INV); sum += wv[s]; }
        float inv = 1.f / sum;
        int qq = qbase + tid;
        #pragma unroll
        for (int s = 0; s < KNN; s++) {
            oi[qq * KNN + s] = seli[s];
            ow[qq * KNN + s] = wv[s] * inv;
        }
    }
}

// ---------------- negative sampling: threshold filter + rank select (block per row) ----------------
// Top-32 of the masked noise row. All unmasked values > 0.98 are collected (expected ~82);
// if >= 32 candidates, the global top-32 are all among them (any top-32 element >= the 32nd
// candidate > 0.98). Fallback pass with threshold -2 guarantees exactness in the tail case.
__global__ __launch_bounds__(256) void k_negs(const float* __restrict__ noise) {
    __shared__ float cv[NPTS];
    __shared__ int   ci[NPTS];
    __shared__ int   s_cnt;
    __shared__ int   s_nb[KNN];
    int r = blockIdx.x, tid = threadIdx.x;
    if (tid == 0) s_cnt = 0;
    if (tid < KNN) s_nb[tid] = g_ir[r * KNN + tid];
    __syncthreads();

    const float4* row4 = (const float4*)(noise + (size_t)r * NPTS);
    for (int pass = 0; pass < 2; pass++) {
        float thresh = pass ? -2.0f : NEG_THRESH;
        #pragma unroll
        for (int k = 0; k < 4; k++) {
            int i4 = tid + 256 * k;
            float4 v = row4[i4];
            float vals[4] = {v.x, v.y, v.z, v.w};
            #pragma unroll
            for (int e = 0; e < 4; e++) {
                float val = vals[e];
                int idx = 4 * i4 + e;
                if (val > thresh && idx != r) {
                    bool nb = false;
                    #pragma unroll
                    for (int t = 0; t < KNN; t++) nb |= (s_nb[t] == idx);
                    if (!nb) {
                        int p = atomicAdd(&s_cnt, 1);
                        cv[p] = val; ci[p] = idx;
                    }
                }
            }
        }
        __syncthreads();
        if (s_cnt >= NNEG) break;
        if (tid == 0) s_cnt = 0;   // fallback: rescan everything
        __syncthreads();
    }

    int ncand = s_cnt;
    // rank = #elements strictly greater (ties broken by lower index, matching top_k)
    for (int i = tid; i < ncand; i += 256) {
        float vi = cv[i]; int ii = ci[i];
        int rank = 0;
        for (int j = 0; j < ncand; j++) {
            float vj = cv[j];
            rank += (vj > vi) || (vj == vi && ci[j] < ii);
        }
        if (rank < NNEG) g_ineg[r * NNEG + rank] = ii;
    }
}

// ---------------- align-KL + attraction + repulsion + Laplacian cross (warp per row) ----------------
__global__ __launch_bounds__(128) void k_pair() {
    int warp = threadIdx.x >> 5, lane = threadIdx.x & 31;
    int r = blockIdx.x * 4 + warp;
    float q0 = g_za[r * DIM + lane], q1 = g_za[r * DIM + 32 + lane];
    int   irv = (lane < KNN) ? g_ir[r * KNN + lane] : 0;
    float wrv = (lane < KNN) ? g_wr[r * KNN + lane] : 0.f;
    int   iav = (lane < KNN) ? g_ia[r * KNN + lane] : -1;
    float wav = (lane < KNN) ? g_wa[r * KNN + lane] : 0.f;
    float anr = g_anorm[r];
    float align_s = 0.f, attr_s = 0.f, lap_s = 0.f, rep_s = 0.f;

    for (int t = 0; t < KNN; t++) {
        int   j  = __shfl_sync(FULLMASK, irv, t);
        float tw = __shfl_sync(FULLMASK, wrv, t);
        float d = q0 * g_za[j * DIM + lane] + q1 * g_za[j * DIM + 32 + lane];
        #pragma unroll
        for (int o = 16; o; o >>= 1) d += __shfl_xor_sync(FULLMASK, d, o);
        unsigned bl = __ballot_sync(FULLMASK, (lane < KNN) && (iav == j));
        float aeq = 0.f;
        if (bl) aeq = __shfl_sync(FULLMASK, wav, __ffs(bl) - 1);
        if (lane == 0) {
            attr_s  += 1.f - d;
            lap_s   += anr * g_anorm[j] * d;
            align_s += tw * (logf(tw) - logf(aeq + 1e-8f));
        }
    }
    for (int m = 0; m < NNEG; m++) {
        int j = g_ineg[r * NNEG + m];
        float d = q0 * g_za[j * DIM + lane] + q1 * g_za[j * DIM + 32 + lane];
        #pragma unroll
        for (int o = 16; o; o >>= 1) d += __shfl_xor_sync(FULLMASK, d, o);
        if (lane == 0) rep_s += fmaxf(MARGIN - (1.f - d), 0.f);
    }
    if (lane == 0) {
        atomicAdd(&g_acc[0], (double)align_s);
        atomicAdd(&g_acc[1], (double)(attr_s / (float)KNN));
        atomicAdd(&g_acc[2], (double)rep_s);
        atomicAdd(&g_acc[3], (double)lap_s);
    }
}

// ---------------- PPR step 1 sparse-sparse: X1 = 64*(0.8*A@A + 0.2*A) -> g_S8 (fp8) ----------------
__global__ __launch_bounds__(256) void k_ppr_first() {
    __shared__ float srow[NPTS];
    __shared__ int sj[KNN]; __shared__ float sw_[KNN];
    int r = blockIdx.x, tid = threadIdx.x;
    if (tid < KNN) { sj[tid] = g_ir[r * KNN + tid]; sw_[tid] = g_wr[r * KNN + tid]; }
    float4* sr4 = (float4*)srow;
    float4 z = {0.f, 0.f, 0.f, 0.f};
    #pragma unroll
    for (int k = 0; k < 4; k++) sr4[tid + 256 * k] = z;
    __syncthreads();
    if (tid < KNN * KNN) {
        int t = tid / KNN, u = tid % KNN;
        int j = sj[t];
        atomicAdd(&srow[g_ir[j * KNN + u]], 0.8f * sw_[t] * g_wr[j * KNN + u]);
    }
    if (tid < KNN) atomicAdd(&srow[sj[tid]], 0.2f * sw_[tid]);
    __syncthreads();
    uint4 ov;
    __nv_fp8x2_storage_t* po = (__nv_fp8x2_storage_t*)&ov;
    #pragma unroll
    for (int e = 0; e < 8; e++) {
        float2 f;
        f.x = PPR_SCALE * srow[16 * tid + 2 * e];
        f.y = PPR_SCALE * srow[16 * tid + 2 * e + 1];
        po[e] = __nv_cvt_float2_to_fp8x2(f, __NV_SATFINITE, __NV_E4M3);
    }
    ((uint4*)(g_S8 + (size_t)r * NPTS))[tid] = ov;
}

// ---------------- dense PPR iteration (fp8 S, half2 accumulate): X' = 0.8*A@X + 12.8*A ----------------
__global__ __launch_bounds__(256) void k_ppr_iter(int it) {
    const unsigned char* __restrict__ src = (it & 1) ? g_T8 : g_S8;
    unsigned char* __restrict__ dst       = (it & 1) ? g_S8 : g_T8;
    int r = blockIdx.x, tid = threadIdx.x;
    __shared__ int sj[KNN]; __shared__ float sw_[KNN];
    if (tid < KNN) { sj[tid] = g_ir[r * KNN + tid]; sw_[tid] = g_wr[r * KNN + tid]; }
    __syncthreads();
    int rj[KNN]; __half2 rw[KNN];
    #pragma unroll
    for (int t = 0; t < KNN; t++) { rj[t] = sj[t]; rw[t] = __float2half2_rn(sw_[t]); }

    const uint4* s4 = (const uint4*)src;   // 256 uint4 (4096 fp8) per row
    __half2 acc[8];
    #pragma unroll
    for (int e = 0; e < 8; e++) acc[e] = __float2half2_rn(0.f);
    #pragma unroll
    for (int t = 0; t < KNN; t++) {
        uint4 v = s4[(size_t)rj[t] * 256 + tid];
        const __nv_fp8x2_storage_t* pv = (const __nv_fp8x2_storage_t*)&v;
        #pragma unroll
        for (int e = 0; e < 8; e++) {
            __half2_raw hr = __nv_cvt_fp8x2_to_halfraw2(pv[e], __NV_E4M3);
            acc[e] = __hfma2(*(__half2*)&hr, rw[t], acc[e]);
        }
    }
    __half2 c08 = __float2half2_rn(0.8f);
    uint4 ov;
    __nv_fp8x2_storage_t* po = (__nv_fp8x2_storage_t*)&ov;
    #pragma unroll
    for (int e = 0; e < 8; e++) {
        __half2 o = __hmul2(acc[e], c08);
        po[e] = __nv_cvt_halfraw2_to_fp8x2(*(__half2_raw*)&o, __NV_SATFINITE, __NV_E4M3);
    }
    ((uint4*)(dst + (size_t)r * NPTS))[tid] = ov;
    __syncthreads();
    if (tid < KNN) {
        size_t p = (size_t)r * NPTS + sj[tid];
        __half_raw h = __nv_cvt_fp8_to_halfraw(dst[p], __NV_E4M3);
        float val = __half2float(*(__half*)&h) + 0.2f * PPR_SCALE * sw_[tid];
        dst[p] = __nv_cvt_float_to_fp8(val, __NV_SATFINITE, __NV_E4M3);
    }
}

// ---------------- row-normalize S and accumulate diff = sum (A_atac - S_hat)^2 ----------------
__global__ __launch_bounds__(256) void k_ppr_final() {
    const unsigned char* __restrict__ S = g_S8;   // after 4 dense iters, final lives in g_S8
    int r = blockIdx.x, tid = threadIdx.x;
    uint4 v = ((const uint4*)(S + (size_t)r * NPTS))[tid];
    const __nv_fp8x2_storage_t* pv = (const __nv_fp8x2_storage_t*)&v;
    float sum = 0.f, sq = 0.f;
    #pragma unroll
    for (int e = 0; e < 8; e++) {
        __half2_raw hr = __nv_cvt_fp8x2_to_halfraw2(pv[e], __NV_E4M3);
        float2 f = __half22float2(*(__half2*)&hr);
        sum += f.x + f.y;
        sq  += f.x * f.x + f.y * f.y;
    }
    __shared__ float s1[256], s2[256];
    s1[tid] = sum; s2[tid] = sq;
    __syncthreads();
    for (int o = 128; o; o >>= 1) {
        if (tid < o) { s1[tid] += s1[tid + o]; s2[tid] += s2[tid + o]; }
        __syncthreads();
    }
    if (tid == 0) {
        float rs = s1[0] * (1.f / PPR_SCALE);
        float rq = s2[0] * (1.f / (PPR_SCALE * PPR_SCALE));
        float rinv = 1.f / fmaxf(rs, 1e-8f);
        float cross = 0.f, a2 = 0.f;
        for (int t = 0; t < KNN; t++) {
            int c = g_ia[r * KNN + t];
            float a = g_wa[r * KNN + t];
            __half_raw h = __nv_cvt_fp8_to_halfraw(S[(size_t)r * NPTS + c], __NV_E4M3);
            cross += a * __half2float(*(__half*)&h) * (1.f / PPR_SCALE);
            a2 += a * a;
        }
        double rowdiff = (double)rq * rinv * rinv - 2.0 * (double)rinv * (double)cross + (double)a2;
        atomicAdd(&g_acc[5], rowdiff);
    }
}

// ---------------- combine ----------------
__global__ void k_final(float* out) {
    double align = g_acc[0] / 4096.0;
    double attr  = g_acc[1] / 4096.0;
    double rep   = g_acc[2] / (4096.0 * 32.0);
    double lap   = (g_acc[4] - g_acc[3] / 15.0) / 4096.0;
    double diff  = g_acc[5] / (4096.0 * 4096.0);
    out[0] = (float)(align + (attr + rep) + 0.5 * lap + 0.5 * diff);
}

extern "C" void kernel_launch(void* const* d_in, const int* in_sizes, int n_in,
                              void* d_out, int out_size) {
    (void)in_sizes; (void)n_in; (void)out_size;
    const float* zr    = (const float*)d_in[0];
    const float* za    = (const float*)d_in[1];
    const float* noise = (const float*)d_in[2];
    float* out = (float*)d_out;

    const int SMEM_TOPK = (64 * QSTR + 64 * KSTR + 64 * KSTR) * (int)sizeof(float); // 84992 B
    cudaFuncSetAttribute(k_topk2, cudaFuncAttributeMaxDynamicSharedMemorySize, SMEM_TOPK);

    k_zero<<<1, 32>>>();
    k_norm<<<NPTS / 4, 128>>>(zr, za);
    k_topk2<<<dim3(64, 2), 256, SMEM_TOPK>>>();   // both graphs fused
    k_negs<<<NPTS, 256>>>(noise);
    k_pair<<<NPTS / 4, 128>>>();
    k_ppr_first<<<NPTS, 256>>>();                 // X1 -> g_S8
    for (int it = 0; it < 4; it++)                // X2..X5
        k_ppr_iter<<<NPTS, 256>>>(it);            // final -> g_S8
    k_ppr_final<<<NPTS, 256>>>();
    k_final<<<1, 1>>>(out);
}

// round 7
// speedup vs baseline: 1.7427x; 1.0345x over previous
#include <cuda_runtime.h>
#include <cuda_fp16.h>
#include <cuda_fp8.h>
#include <math.h>

#define NPTS 4096
#define DIM  64
#define KNN  15
#define NNEG 32
#define TEMP_INV 10.0f
#define MARGIN 0.5f
#define FULLMASK 0xffffffffu
#define NEG_THRESH 0.98f
#define PPR_SCALE 64.0f

// ---------------- device scratch (allocation-free per rules) ----------------
__device__ float g_zr[NPTS * DIM];        // normalized z_rna
__device__ float g_za[NPTS * DIM];        // normalized z_atac
__device__ float g_anorm[NPTS];           // raw ||z_atac_i||
__device__ int   g_ir[NPTS * KNN];        // rna knn indices
__device__ float g_wr[NPTS * KNN];        // rna softmax weights
__device__ int   g_ia[NPTS * KNN];        // atac knn indices
__device__ float g_wa[NPTS * KNN];        // atac softmax weights
__device__ int   g_ineg[NPTS * NNEG];     // negative sample indices
__device__ float g_cv2[2 * NPTS * 2 * 16];   // topk half-candidates (values)
__device__ int   g_ci2[2 * NPTS * 2 * 16];   // topk half-candidates (indices)
__device__ unsigned char g_S8[(size_t)NPTS * NPTS];  // 16MB ping (fp8 e4m3, stores 64*S)
__device__ unsigned char g_T8[(size_t)NPTS * NPTS];  // 16MB pong
__device__ double g_acc[8];               // 0:align 1:attr 2:rep 3:lap_cross 4:fro 5:diff

// ---------------- zero accumulators ----------------
__global__ void k_zero() {
    if (threadIdx.x < 8) g_acc[threadIdx.x] = 0.0;
}

// ---------------- normalize rows, collect raw atac norms + Frobenius ----------------
__global__ __launch_bounds__(128) void k_norm(const float* __restrict__ zr,
                                              const float* __restrict__ za) {
    int warp = threadIdx.x >> 5, lane = threadIdx.x & 31;
    int r = blockIdx.x * 4 + warp;
    float a0 = zr[r * DIM + lane],      a1 = zr[r * DIM + 32 + lane];
    float b0 = za[r * DIM + lane],      b1 = za[r * DIM + 32 + lane];
    float sr = a0 * a0 + a1 * a1;
    float sa = b0 * b0 + b1 * b1;
    #pragma unroll
    for (int o = 16; o; o >>= 1) {
        sr += __shfl_xor_sync(FULLMASK, sr, o);
        sa += __shfl_xor_sync(FULLMASK, sa, o);
    }
    float nr = fmaxf(sqrtf(sr), 1e-12f);
    float na = fmaxf(sqrtf(sa), 1e-12f);
    g_zr[r * DIM + lane]      = a0 / nr;
    g_zr[r * DIM + 32 + lane] = a1 / nr;
    g_za[r * DIM + lane]      = b0 / na;
    g_za[r * DIM + 32 + lane] = b1 / na;
    if (lane == 0) {
        g_anorm[r] = na;
        atomicAdd(&g_acc[4], (double)sa);   // Frobenius^2 of raw z_atac
    }
}

// ---------------- register-tiled sim GEMM + per-half top-15, both graphs ----------------
// grid (64, 2, 2): x = query tile (64 q), y = which graph, z = key half (2048 keys).
#define QSTR 68    // Qt row stride in floats (17 granules)
#define KSTR 132   // Kt/Sc row stride in floats (33 granules)

__global__ __launch_bounds__(256, 2) void k_topk2() {
    extern __shared__ __align__(16) float smem[];
    float* Qt = smem;                    // 64 * 68  = 4352 floats
    float* Kt = smem + 64 * QSTR;        // 64 * 132 = 8448 floats
    float* Sc = Kt + 64 * KSTR;          // 64 * 132 = 8448 floats
    float4* Qt4 = (float4*)Qt;
    float4* Kt4 = (float4*)Kt;
    float4* Sc4 = (float4*)Sc;

    int which = blockIdx.y;
    int bz = blockIdx.z;
    const float* __restrict__ Zn = which ? g_za : g_zr;
    const float4* Zn4 = (const float4*)Zn;

    int tid = threadIdx.x;
    int tx = tid & 15, ty = tid >> 4;
    int qbase = blockIdx.x * 64;
    int q_loc = tid >> 2, part = tid & 3;
    int q_self = qbase + q_loc;

    // ---- load + transpose Q tile (64 q x 64 d), swizzled ----
    #pragma unroll
    for (int l = 0; l < 4; l++) {
        int idx = tid + l * 256;
        int q = idx >> 4, d4 = idx & 15;
        float4 v = Zn4[(qbase + q) * 16 + d4];
        int qg = q >> 2, qr = q & 3;
        int sw = d4 & 7;
        int base = ((qg ^ sw) << 2) + qr;
        Qt[(4 * d4 + 0) * QSTR + base] = v.x;
        Qt[(4 * d4 + 1) * QSTR + base] = v.y;
        Qt[(4 * d4 + 2) * QSTR + base] = v.z;
        Qt[(4 * d4 + 3) * QSTR + base] = v.w;
    }

    float tv[KNN]; int ti[KNN];
    #pragma unroll
    for (int u = 0; u < KNN; u++) { tv[u] = -1e30f; ti[u] = 0; }
    float vmin = -1e30f; int pmin = 0;

    for (int kt = bz * 16; kt < bz * 16 + 16; kt++) {
        int kbase = kt * 128;
        __syncthreads();   // prev insert done; safe to overwrite Kt
        // ---- load + transpose K tile (128 k x 64 d), swizzled ----
        #pragma unroll
        for (int l = 0; l < 8; l++) {
            int idx = tid + l * 256;
            int k = idx >> 4, d4 = idx & 15;
            float4 v = Zn4[(kbase + k) * 16 + d4];
            int kg = k >> 2, kr = k & 3;
            int sw = d4 & 7;
            int base = ((kg ^ sw) << 2) + kr;
            Kt[(4 * d4 + 0) * KSTR + base] = v.x;
            Kt[(4 * d4 + 1) * KSTR + base] = v.y;
            Kt[(4 * d4 + 2) * KSTR + base] = v.z;
            Kt[(4 * d4 + 3) * KSTR + base] = v.w;
        }
        __syncthreads();

        // ---- compute 4x8 register tile ----
        float acc[4][8];
        #pragma unroll
        for (int i = 0; i < 4; i++)
            #pragma unroll
            for (int j = 0; j < 8; j++) acc[i][j] = 0.f;

        #pragma unroll 4
        for (int d = 0; d < 64; d++) {
            int w = (d >> 2) & 7;
            float4 a  = Qt4[d * 17 + (ty ^ w)];
            float4 b0 = Kt4[d * 33 + (tx ^ w)];
            float4 b1 = Kt4[d * 33 + 16 + (tx ^ w)];
            float av[4] = {a.x, a.y, a.z, a.w};
            float bv[8] = {b0.x, b0.y, b0.z, b0.w, b1.x, b1.y, b1.z, b1.w};
            #pragma unroll
            for (int i = 0; i < 4; i++)
                #pragma unroll
                for (int j = 0; j < 8; j++)
                    acc[i][j] = fmaf(av[i], bv[j], acc[i][j]);
        }

        // ---- write score tile ----
        #pragma unroll
        for (int i = 0; i < 4; i++) {
            float4 s0; s0.x = acc[i][0]; s0.y = acc[i][1]; s0.z = acc[i][2]; s0.w = acc[i][3];
            float4 s1; s1.x = acc[i][4]; s1.y = acc[i][5]; s1.z = acc[i][6]; s1.w = acc[i][7];
            Sc4[(ty * 4 + i) * 33 + tx]      = s0;
            Sc4[(ty * 4 + i) * 33 + 16 + tx] = s1;
        }
        __syncthreads();

        // ---- insert: 4 threads/query, each scans 32 cols (bank-staggered) ----
        int rowb = q_loc * KSTR + part * 32;
        int colb = kbase + part * 32;
        #pragma unroll 4
        for (int c0 = 0; c0 < 32; c0++) {
            int c = (c0 + part * 8) & 31;
            float v = Sc[rowb + c];
            int jg = colb + c;
            if (jg != q_self && v > vmin) {
                tv[pmin] = v; ti[pmin] = jg;
                vmin = tv[0]; pmin = 0;
                #pragma unroll
                for (int u = 1; u < KNN; u++)
                    if (tv[u] < vmin) { vmin = tv[u]; pmin = u; }
            }
        }
    }
    __syncthreads();

    // ---- merge 4 per-part lists (60 candidates/query), emit half top-15 ----
    float* candv = smem;                      // overlays Qt
    int*   candi = (int*)(smem + 64 * QSTR);  // overlays Kt
    int cb = q_loc * 60 + part * KNN;
    #pragma unroll
    for (int u = 0; u < KNN; u++) { candv[cb + u] = tv[u]; candi[cb + u] = ti[u]; }
    __syncthreads();

    if (tid < 64) {
        int b = tid * 60;
        int qq = qbase + tid;
        size_t ob = ((size_t)(which * NPTS + qq) * 2 + bz) * 16;
        for (int s = 0; s < KNN; s++) {
            float bv = -2e30f; int bp = 0;
            for (int c = 0; c < 60; c++) {
                float v = candv[b + c];
                if (v > bv) { bv = v; bp = c; }
            }
            g_cv2[ob + s] = bv;
            g_ci2[ob + s] = candi[b + bp];
            candv[b + bp] = -3e30f;
        }
    }
}

// ---------------- merge key-halves, softmax, write final knn graph ----------------
__global__ __launch_bounds__(256) void k_topk_merge() {
    int g = blockIdx.x * 256 + threadIdx.x;   // 0..8191
    int which = g >> 12, q = g & (NPTS - 1);
    int*   __restrict__ oi = which ? g_ia : g_ir;
    float* __restrict__ ow = which ? g_wa : g_wr;
    size_t cb = (size_t)(which * NPTS + q) * 32;
    float cv[30]; int ci[30];
    #pragma unroll
    for (int s = 0; s < KNN; s++) {
        cv[s]       = g_cv2[cb + s];      ci[s]       = g_ci2[cb + s];
        cv[KNN + s] = g_cv2[cb + 16 + s]; ci[KNN + s] = g_ci2[cb + 16 + s];
    }
    unsigned used = 0;
    float selv[KNN]; int seli[KNN];
    #pragma unroll
    for (int s = 0; s < KNN; s++) {
        float bvv = -2e30f; int bii = 0x7fffffff; int bj = 0;
        #pragma unroll
        for (int j = 0; j < 30; j++) {
            bool ok = !((used >> j) & 1u);
            bool better = ok && ((cv[j] > bvv) || (cv[j] == bvv && ci[j] < bii));
            if (better) { bvv = cv[j]; bii = ci[j]; bj = j; }
        }
        used |= 1u << bj;
        selv[s] = bvv; seli[s] = bii;
    }
    float m = selv[0], sum = 0.f;
    float wv[KNN];
    #pragma unroll
    for (int s = 0; s < KNN; s++) { wv[s] = expf((selv[s] - m) * TEMP_INV); sum += wv[s]; }
    float inv = 1.f / sum;
    #pragma unroll
    for (int s = 0; s < KNN; s++) {
        oi[q * KNN + s] = seli[s];
        ow[q * KNN + s] = wv[s] * inv;
    }
}

// ---------------- negative sampling: ballot-compacted threshold filter (block per row) ----------------
__global__ __launch_bounds__(256) void k_negs(const float* __restrict__ noise) {
    __shared__ float cv[NPTS];
    __shared__ int   ci[NPTS];
    __shared__ int   s_cnt, s_valid;
    __shared__ int   s_nb[KNN];
    int r = blockIdx.x, tid = threadIdx.x, lane = tid & 31;
    if (tid == 0) { s_cnt = 0; s_valid = 0; }
    if (tid < KNN) s_nb[tid] = g_ir[r * KNN + tid];
    __syncthreads();

    const float4* row4 = (const float4*)(noise + (size_t)r * NPTS);
    float4 v[4];
    #pragma unroll
    for (int k = 0; k < 4; k++) v[k] = row4[tid + 256 * k];

    // phase 1: collect all values > thresh (mask deferred), warp-ballot compaction
    #pragma unroll
    for (int k = 0; k < 4; k++) {
        float vals[4] = {v[k].x, v[k].y, v[k].z, v[k].w};
        #pragma unroll
        for (int e = 0; e < 4; e++) {
            int idx = 4 * (tid + 256 * k) + e;
            bool f = (vals[e] > NEG_THRESH) && (idx != r);
            unsigned bal = __ballot_sync(FULLMASK, f);
            if (bal) {
                int wbase;
                if (lane == 0) wbase = atomicAdd(&s_cnt, __popc(bal));
                wbase = __shfl_sync(FULLMASK, wbase, 0);
                if (f) {
                    int pos = wbase + __popc(bal & ((1u << lane) - 1u));
                    cv[pos] = vals[e]; ci[pos] = idx;
                }
            }
        }
    }
    __syncthreads();
    int cnt = s_cnt;

    // phase 2: mark rna-neighbors invalid, count survivors
    {
        int c = 0;
        for (int i = tid; i < cnt; i += 256) {
            int ii = ci[i];
            bool nb = false;
            #pragma unroll
            for (int t = 0; t < KNN; t++) nb |= (s_nb[t] == ii);
            if (nb) cv[i] = -10.f; else c++;
        }
        #pragma unroll
        for (int o = 16; o; o >>= 1) c += __shfl_xor_sync(FULLMASK, c, o);
        if (lane == 0 && c) atomicAdd(&s_valid, c);
    }
    __syncthreads();

    // fallback (probability ~0): collect every unmasked element
    if (s_valid < NNEG) {
        if (tid == 0) s_cnt = 0;
        __syncthreads();
        #pragma unroll
        for (int k = 0; k < 4; k++) {
            float vals[4] = {v[k].x, v[k].y, v[k].z, v[k].w};
            #pragma unroll
            for (int e = 0; e < 4; e++) {
                int idx = 4 * (tid + 256 * k) + e;
                bool nb = (idx == r);
                #pragma unroll
                for (int t = 0; t < KNN; t++) nb |= (s_nb[t] == idx);
                if (!nb) {
                    int p = atomicAdd(&s_cnt, 1);
                    cv[p] = vals[e]; ci[p] = idx;
                }
            }
        }
        __syncthreads();
        cnt = s_cnt;
    }

    // phase 3: rank select (top_k semantics: value desc, index asc on ties)
    for (int i = tid; i < cnt; i += 256) {
        float vi = cv[i]; int ii = ci[i];
        if (vi <= -5.f) continue;
        int rank = 0;
        for (int j = 0; j < cnt; j++) {
            float vj = cv[j];
            rank += (vj > vi) || (vj == vi && ci[j] < ii);
        }
        if (rank < NNEG) g_ineg[r * NNEG + rank] = ii;
    }
}

// ---------------- align-KL + attraction + repulsion + Laplacian cross (warp per row) ----------------
__global__ __launch_bounds__(128) void k_pair() {
    int warp = threadIdx.x >> 5, lane = threadIdx.x & 31;
    int r = blockIdx.x * 4 + warp;
    float q0 = g_za[r * DIM + lane], q1 = g_za[r * DIM + 32 + lane];
    int   irv = (lane < KNN) ? g_ir[r * KNN + lane] : 0;
    float wrv = (lane < KNN) ? g_wr[r * KNN + lane] : 0.f;
    int   iav = (lane < KNN) ? g_ia[r * KNN + lane] : -1;
    float wav = (lane < KNN) ? g_wa[r * KNN + lane] : 0.f;
    float anr = g_anorm[r];
    float align_s = 0.f, attr_s = 0.f, lap_s = 0.f, rep_s = 0.f;

    for (int t = 0; t < KNN; t++) {
        int   j  = __shfl_sync(FULLMASK, irv, t);
        float tw = __shfl_sync(FULLMASK, wrv, t);
        float d = q0 * g_za[j * DIM + lane] + q1 * g_za[j * DIM + 32 + lane];
        #pragma unroll
        for (int o = 16; o; o >>= 1) d += __shfl_xor_sync(FULLMASK, d, o);
        unsigned bl = __ballot_sync(FULLMASK, (lane < KNN) && (iav == j));
        float aeq = 0.f;
        if (bl) aeq = __shfl_sync(FULLMASK, wav, __ffs(bl) - 1);
        if (lane == 0) {
            attr_s  += 1.f - d;
            lap_s   += anr * g_anorm[j] * d;
            align_s += tw * (logf(tw) - logf(aeq + 1e-8f));
        }
    }
    for (int m = 0; m < NNEG; m++) {
        int j = g_ineg[r * NNEG + m];
        float d = q0 * g_za[j * DIM + lane] + q1 * g_za[j * DIM + 32 + lane];
        #pragma unroll
        for (int o = 16; o; o >>= 1) d += __shfl_xor_sync(FULLMASK, d, o);
        if (lane == 0) rep_s += fmaxf(MARGIN - (1.f - d), 0.f);
    }
    if (lane == 0) {
        atomicAdd(&g_acc[0], (double)align_s);
        atomicAdd(&g_acc[1], (double)(attr_s / (float)KNN));
        atomicAdd(&g_acc[2], (double)rep_s);
        atomicAdd(&g_acc[3], (double)lap_s);
    }
}

// ---------------- PPR step 1 sparse-sparse: X1 = 64*(0.8*A@A + 0.2*A) -> g_S8 (fp8) ----------------
__global__ __launch_bounds__(256) void k_ppr_first() {
    __shared__ float srow[NPTS];
    __shared__ int sj[KNN]; __shared__ float sw_[KNN];
    int r = blockIdx.x, tid = threadIdx.x;
    if (tid < KNN) { sj[tid] = g_ir[r * KNN + tid]; sw_[tid] = g_wr[r * KNN + tid]; }
    float4* sr4 = (float4*)srow;
    float4 z = {0.f, 0.f, 0.f, 0.f};
    #pragma unroll
    for (int k = 0; k < 4; k++) sr4[tid + 256 * k] = z;
    __syncthreads();
    if (tid < KNN * KNN) {
        int t = tid / KNN, u = tid % KNN;
        int j = sj[t];
        atomicAdd(&srow[g_ir[j * KNN + u]], 0.8f * sw_[t] * g_wr[j * KNN + u]);
    }
    if (tid < KNN) atomicAdd(&srow[sj[tid]], 0.2f * sw_[tid]);
    __syncthreads();
    uint4 ov;
    __nv_fp8x2_storage_t* po = (__nv_fp8x2_storage_t*)&ov;
    #pragma unroll
    for (int e = 0; e < 8; e++) {
        float2 f;
        f.x = PPR_SCALE * srow[16 * tid + 2 * e];
        f.y = PPR_SCALE * srow[16 * tid + 2 * e + 1];
        po[e] = __nv_cvt_float2_to_fp8x2(f, __NV_SATFINITE, __NV_E4M3);
    }
    ((uint4*)(g_S8 + (size_t)r * NPTS))[tid] = ov;
}

// ---------------- dense PPR iteration (fp8 S, half2 accumulate): X' = 0.8*A@X + 12.8*A ----------------
__global__ __launch_bounds__(256) void k_ppr_iter(int it) {
    const unsigned char* __restrict__ src = (it & 1) ? g_T8 : g_S8;
    unsigned char* __restrict__ dst       = (it & 1) ? g_S8 : g_T8;
    int r = blockIdx.x, tid = threadIdx.x;
    __shared__ int sj[KNN]; __shared__ float sw_[KNN];
    if (tid < KNN) { sj[tid] = g_ir[r * KNN + tid]; sw_[tid] = g_wr[r * KNN + tid]; }
    __syncthreads();
    int rj[KNN]; __half2 rw[KNN];
    #pragma unroll
    for (int t = 0; t < KNN; t++) { rj[t] = sj[t]; rw[t] = __float2half2_rn(sw_[t]); }

    const uint4* s4 = (const uint4*)src;   // 256 uint4 (4096 fp8) per row
    __half2 acc[8];
    #pragma unroll
    for (int e = 0; e < 8; e++) acc[e] = __float2half2_rn(0.f);
    #pragma unroll
    for (int t = 0; t < KNN; t++) {
        uint4 v = s4[(size_t)rj[t] * 256 + tid];
        const __nv_fp8x2_storage_t* pv = (const __nv_fp8x2_storage_t*)&v;
        #pragma unroll
        for (int e = 0; e < 8; e++) {
            __half2_raw hr = __nv_cvt_fp8x2_to_halfraw2(pv[e], __NV_E4M3);
            acc[e] = __hfma2(*(__half2*)&hr, rw[t], acc[e]);
        }
    }
    __half2 c08 = __float2half2_rn(0.8f);
    uint4 ov;
    __nv_fp8x2_storage_t* po = (__nv_fp8x2_storage_t*)&ov;
    #pragma unroll
    for (int e = 0; e < 8; e++) {
        __half2 o = __hmul2(acc[e], c08);
        po[e] = __nv_cvt_halfraw2_to_fp8x2(*(__half2_raw*)&o, __NV_SATFINITE, __NV_E4M3);
    }
    ((uint4*)(dst + (size_t)r * NPTS))[tid] = ov;
    __syncthreads();
    if (tid < KNN) {
        size_t p = (size_t)r * NPTS + sj[tid];
        __half_raw h = __nv_cvt_fp8_to_halfraw(dst[p], __NV_E4M3);
        float val = __half2float(*(__half*)&h) + 0.2f * PPR_SCALE * sw_[tid];
        dst[p] = __nv_cvt_float_to_fp8(val, __NV_SATFINITE, __NV_E4M3);
    }
}

// ---------------- row-normalize S and accumulate diff = sum (A_atac - S_hat)^2 ----------------
__global__ __launch_bounds__(256) void k_ppr_final() {
    const unsigned char* __restrict__ S = g_S8;   // after 4 dense iters, final lives in g_S8
    int r = blockIdx.x, tid = threadIdx.x;
    uint4 v = ((const uint4*)(S + (size_t)r * NPTS))[tid];
    const __nv_fp8x2_storage_t* pv = (const __nv_fp8x2_storage_t*)&v;
    float sum = 0.f, sq = 0.f;
    #pragma unroll
    for (int e = 0; e < 8; e++) {
        __half2_raw hr = __nv_cvt_fp8x2_to_halfraw2(pv[e], __NV_E4M3);
        float2 f = __half22float2(*(__half2*)&hr);
        sum += f.x + f.y;
        sq  += f.x * f.x + f.y * f.y;
    }
    __shared__ float s1[256], s2[256];
    s1[tid] = sum; s2[tid] = sq;
    __syncthreads();
    for (int o = 128; o; o >>= 1) {
        if (tid < o) { s1[tid] += s1[tid + o]; s2[tid] += s2[tid + o]; }
        __syncthreads();
    }
    if (tid == 0) {
        float rs = s1[0] * (1.f / PPR_SCALE);
        float rq = s2[0] * (1.f / (PPR_SCALE * PPR_SCALE));
        float rinv = 1.f / fmaxf(rs, 1e-8f);
        float cross = 0.f, a2 = 0.f;
        for (int t = 0; t < KNN; t++) {
            int c = g_ia[r * KNN + t];
            float a = g_wa[r * KNN + t];
            __half_raw h = __nv_cvt_fp8_to_halfraw(S[(size_t)r * NPTS + c], __NV_E4M3);
            cross += a * __half2float(*(__half*)&h) * (1.f / PPR_SCALE);
            a2 += a * a;
        }
        double rowdiff = (double)rq * rinv * rinv - 2.0 * (double)rinv * (double)cross + (double)a2;
        atomicAdd(&g_acc[5], rowdiff);
    }
}

// ---------------- combine ----------------
__global__ void k_final(float* out) {
    double align = g_acc[0] / 4096.0;
    double attr  = g_acc[1] / 4096.0;
    double rep   = g_acc[2] / (4096.0 * 32.0);
    double lap   = (g_acc[4] - g_acc[3] / 15.0) / 4096.0;
    double diff  = g_acc[5] / (4096.0 * 4096.0);
    out[0] = (float)(align + (attr + rep) + 0.5 * lap + 0.5 * diff);
}

extern "C" void kernel_launch(void* const* d_in, const int* in_sizes, int n_in,
                              void* d_out, int out_size) {
    (void)in_sizes; (void)n_in; (void)out_size;
    const float* zr    = (const float*)d_in[0];
    const float* za    = (const float*)d_in[1];
    const float* noise = (const float*)d_in[2];
    float* out = (float*)d_out;

    const int SMEM_TOPK = (64 * QSTR + 64 * KSTR + 64 * KSTR) * (int)sizeof(float); // 84992 B
    cudaFuncSetAttribute(k_topk2, cudaFuncAttributeMaxDynamicSharedMemorySize, SMEM_TOPK);

    k_zero<<<1, 32>>>();
    k_norm<<<NPTS / 4, 128>>>(zr, za);
    k_topk2<<<dim3(64, 2, 2), 256, SMEM_TOPK>>>();  // both graphs, key-halved
    k_topk_merge<<<32, 256>>>();
    k_negs<<<NPTS, 256>>>(noise);
    k_pair<<<NPTS / 4, 128>>>();
    k_ppr_first<<<NPTS, 256>>>();                 // X1 -> g_S8
    for (int it = 0; it < 4; it++)                // X2..X5
        k_ppr_iter<<<NPTS, 256>>>(it);            // final -> g_S8
    k_ppr_final<<<NPTS, 256>>>();
    k_final<<<1, 1>>>(out);
}